// round 17
// baseline (speedup 1.0000x reference)
#include <cuda_runtime.h>
#include <cuda_bf16.h>
#include <mma.h>
#include <cstdint>

using namespace nvcuda;

#define N_NODES 100000
#define N_EDGES 1600000
#define NB      1024
#define IN_F    32
#define H_F     64

// ---------------- scratch (device globals; zero-initialized .bss) -----------
__device__ int   g_deg [N_NODES];
__device__ int   g_off [N_NODES];
__device__ int   g_cur [N_NODES];
__device__ int   g_csr [N_EDGES];           // src ids grouped by dst (order-free)
__device__ int   g_total;
__device__ __align__(256) float g_agg1[N_NODES * IN_F];  // 12.8 MB
__device__ __align__(256) float g_agg2[N_NODES * H_F];   // 25.6 MB
__device__ __align__(256) float g_h1  [N_NODES * H_F];   // 25.6 MB
__device__ __align__(256) float g_sum1[NB * H_F];
__device__ __align__(256) float g_sum2[NB * H_F];
__device__ __align__(256) float g_cnt [NB];

__device__ __forceinline__ void red_add_v4(float* addr, float4 v) {
    asm volatile("red.global.add.v4.f32 [%0], {%1, %2, %3, %4};"
                 :: "l"(addr), "f"(v.x), "f"(v.y), "f"(v.z), "f"(v.w)
                 : "memory");
}

__device__ __forceinline__ void split_bf16(float v, __nv_bfloat16& h, __nv_bfloat16& l) {
    h = __float2bfloat16(v);
    l = __float2bfloat16(v - __bfloat162float(h));
}

// ---------------- CSR build: deg -> atomic offsets -> fill -------------------
__global__ void deg_kernel(const int* __restrict__ dst) {
    int e = blockIdx.x * blockDim.x + threadIdx.x;
    if (e < N_EDGES) atomicAdd(&g_deg[__ldg(dst + e)], 1);
}

__global__ void offs_kernel() {
    int n = blockIdx.x * blockDim.x + threadIdx.x;
    if (n >= N_NODES) return;
    int d = g_deg[n];
    int off = atomicAdd(&g_total, d);
    g_off[n] = off;
    g_cur[n] = off;
}

__global__ void fill_kernel(const int* __restrict__ src,
                            const int* __restrict__ dst) {
    int e = blockIdx.x * blockDim.x + threadIdx.x;
    if (e >= N_EDGES) return;
    int d = __ldg(dst + e);
    int pos = atomicAdd(&g_cur[d], 1);
    g_csr[pos] = __ldg(src + e);
}

// ---------------- gather 1: warp per node, lane = feature, unroll 4 ----------
__global__ __launch_bounds__(256)
void gather1_kernel(const float* __restrict__ feat) {
    int n = (blockIdx.x * 256 + threadIdx.x) >> 5;
    int lane = threadIdx.x & 31;
    if (n >= N_NODES) return;
    int st = __ldg(&g_off[n]);
    int dg = __ldg(&g_deg[n]);
    float acc = 0.f;
    int i = 0;
    for (; i + 4 <= dg; i += 4) {
        int s0 = __ldg(g_csr + st + i);
        int s1 = __ldg(g_csr + st + i + 1);
        int s2 = __ldg(g_csr + st + i + 2);
        int s3 = __ldg(g_csr + st + i + 3);
        float a0 = __ldg(feat + (size_t)s0 * IN_F + lane);
        float a1 = __ldg(feat + (size_t)s1 * IN_F + lane);
        float a2 = __ldg(feat + (size_t)s2 * IN_F + lane);
        float a3 = __ldg(feat + (size_t)s3 * IN_F + lane);
        acc += (a0 + a1) + (a2 + a3);
    }
    for (; i < dg; i++) {
        int s = __ldg(g_csr + st + i);
        acc += __ldg(feat + (size_t)s * IN_F + lane);
    }
    g_agg1[(size_t)n * IN_F + lane] = acc;
}

// ---------------- gather 2: warp per node, lane = float2 chunk, unroll 4 -----
__global__ __launch_bounds__(256)
void gather2_kernel() {
    int n = (blockIdx.x * 256 + threadIdx.x) >> 5;
    int lane = threadIdx.x & 31;
    if (n >= N_NODES) return;
    int st = __ldg(&g_off[n]);
    int dg = __ldg(&g_deg[n]);
    const float2* h1v = reinterpret_cast<const float2*>(g_h1);
    float2 acc = make_float2(0.f, 0.f);
    int i = 0;
    for (; i + 4 <= dg; i += 4) {
        int s0 = __ldg(g_csr + st + i);
        int s1 = __ldg(g_csr + st + i + 1);
        int s2 = __ldg(g_csr + st + i + 2);
        int s3 = __ldg(g_csr + st + i + 3);
        float2 a0 = h1v[(size_t)s0 * 32 + lane];
        float2 a1 = h1v[(size_t)s1 * 32 + lane];
        float2 a2 = h1v[(size_t)s2 * 32 + lane];
        float2 a3 = h1v[(size_t)s3 * 32 + lane];
        acc.x += (a0.x + a1.x) + (a2.x + a3.x);
        acc.y += (a0.y + a1.y) + (a2.y + a3.y);
    }
    for (; i < dg; i++) {
        int s = __ldg(g_csr + st + i);
        float2 a = h1v[(size_t)s * 32 + lane];
        acc.x += a.x; acc.y += a.y;
    }
    reinterpret_cast<float2*>(g_agg2)[(size_t)n * 32 + lane] = acc;
}

// ================= WMMA MLP machinery ========================================
// Arena (48 KB): [0,16K) xhT, [16K,32K) xlT, [32K,40K) wh, [40K,48K) wl.
// s_out (fp32, col-major, ld 128, 32 KB) overlays xhT/xlT after the sync.
// xT layout: [K][128] (X^T row-major) = matrix_a col_major, ldm 128.
// w layout: [K][64] row-major = matrix_b row_major, ldm 64.

// stage weights w[K][64] fp32 -> bf16 hi/lo
template<int K>
__device__ __forceinline__ void stage_w(__nv_bfloat16* wh, __nv_bfloat16* wl,
                                        const float* __restrict__ w, int tid) {
    for (int idx = tid; idx < K * 16; idx += 128) {
        int k = idx >> 4, c = idx & 15;
        float4 v = __ldg(reinterpret_cast<const float4*>(w) + k * 16 + c);
        int base = k * 64 + c * 4;
        __nv_bfloat16 h, l;
        split_bf16(v.x, h, l); wh[base]     = h; wl[base]     = l;
        split_bf16(v.y, h, l); wh[base + 1] = h; wl[base + 1] = l;
        split_bf16(v.z, h, l); wh[base + 2] = h; wl[base + 2] = l;
        split_bf16(v.w, h, l); wh[base + 3] = h; wl[base + 3] = l;
    }
}

// one dense layer: D(128x64) = X(128xK) @ W(Kx64), compensated bf16 (hh+hl+lh)
template<int KT>   // K/16
__device__ __forceinline__ void wmma_layer(const __nv_bfloat16* xhT,
                                           const __nv_bfloat16* xlT,
                                           const __nv_bfloat16* wh,
                                           const __nv_bfloat16* wl,
                                           float* s_out, int wid) {
    wmma::fragment<wmma::accumulator, 16, 16, 16, float> acc[2][4];
#pragma unroll
    for (int mt = 0; mt < 2; mt++)
#pragma unroll
        for (int nt = 0; nt < 4; nt++) wmma::fill_fragment(acc[mt][nt], 0.f);
#pragma unroll
    for (int k = 0; k < KT; k++) {
        wmma::fragment<wmma::matrix_a, 16, 16, 16, __nv_bfloat16, wmma::col_major> ah0, ah1, al0, al1;
        wmma::load_matrix_sync(ah0, xhT + k * 16 * 128 + wid * 32,      128);
        wmma::load_matrix_sync(ah1, xhT + k * 16 * 128 + wid * 32 + 16, 128);
        wmma::load_matrix_sync(al0, xlT + k * 16 * 128 + wid * 32,      128);
        wmma::load_matrix_sync(al1, xlT + k * 16 * 128 + wid * 32 + 16, 128);
#pragma unroll
        for (int nt = 0; nt < 4; nt++) {
            wmma::fragment<wmma::matrix_b, 16, 16, 16, __nv_bfloat16, wmma::row_major> bh, bl;
            wmma::load_matrix_sync(bh, wh + k * 16 * 64 + nt * 16, 64);
            wmma::load_matrix_sync(bl, wl + k * 16 * 64 + nt * 16, 64);
            wmma::mma_sync(acc[0][nt], ah0, bh, acc[0][nt]);
            wmma::mma_sync(acc[0][nt], ah0, bl, acc[0][nt]);
            wmma::mma_sync(acc[0][nt], al0, bh, acc[0][nt]);
            wmma::mma_sync(acc[1][nt], ah1, bh, acc[1][nt]);
            wmma::mma_sync(acc[1][nt], ah1, bl, acc[1][nt]);
            wmma::mma_sync(acc[1][nt], al1, bh, acc[1][nt]);
        }
    }
    __syncthreads();   // all x/w reads done before s_out overlays xT
#pragma unroll
    for (int mt = 0; mt < 2; mt++)
#pragma unroll
        for (int nt = 0; nt < 4; nt++)
            wmma::store_matrix_sync(s_out + nt * 16 * 128 + wid * 32 + mt * 16,
                                    acc[mt][nt], 128, wmma::mem_col_major);
    __syncthreads();
}

// ============================================================================
// node MLP 1 (WMMA): x(32)=in_feat+agg1 -> relu(W1 64) -> relu(W2 64)
// writes h1, pools sum1, counts.
// ============================================================================
__global__ __launch_bounds__(128)
void mlp1_kernel(const float* __restrict__ in_feat,
                 const float* __restrict__ w1, const float* __restrict__ b1,
                 const float* __restrict__ w2, const float* __restrict__ b2,
                 const int* __restrict__ gids) {
    __shared__ __align__(16) char arena[49152];
    __nv_bfloat16* xhT = reinterpret_cast<__nv_bfloat16*>(arena);
    __nv_bfloat16* xlT = reinterpret_cast<__nv_bfloat16*>(arena + 16384);
    __nv_bfloat16* wh  = reinterpret_cast<__nv_bfloat16*>(arena + 32768);
    __nv_bfloat16* wl  = reinterpret_cast<__nv_bfloat16*>(arena + 40960);
    float* s_out = reinterpret_cast<float*>(arena);
    const int tid = threadIdx.x, wid = tid >> 5;
    const int nbase = blockIdx.x * 128;

    // stage x = in_feat + agg1, transposed bf16 hi/lo (K=32)
    for (int idx = tid; idx < 128 * 8; idx += 128) {
        int row = idx >> 3, c = idx & 7;
        int node = nbase + row;
        float4 v = make_float4(0.f, 0.f, 0.f, 0.f);
        if (node < N_NODES) {
            float4 a = __ldg(reinterpret_cast<const float4*>(in_feat) + (size_t)node * 8 + c);
            float4 b = *(reinterpret_cast<const float4*>(g_agg1) + (size_t)node * 8 + c);
            v = make_float4(a.x + b.x, a.y + b.y, a.z + b.z, a.w + b.w);
        }
        int col = c * 4;
        __nv_bfloat16 h, l;
        split_bf16(v.x, h, l); xhT[(col    ) * 128 + row] = h; xlT[(col    ) * 128 + row] = l;
        split_bf16(v.y, h, l); xhT[(col + 1) * 128 + row] = h; xlT[(col + 1) * 128 + row] = l;
        split_bf16(v.z, h, l); xhT[(col + 2) * 128 + row] = h; xlT[(col + 2) * 128 + row] = l;
        split_bf16(v.w, h, l); xhT[(col + 3) * 128 + row] = h; xlT[(col + 3) * 128 + row] = l;
    }
    stage_w<32>(wh, wl, w1, tid);
    __syncthreads();

    wmma_layer<2>(xhT, xlT, wh, wl, s_out, wid);

    // t = relu(D + b1); conflict-free col-major readback
    float o[64];
#pragma unroll
    for (int j = 0; j < 64; j++)
        o[j] = fmaxf(s_out[j * 128 + tid] + __ldg(b1 + j), 0.f);
    __syncthreads();   // all s_out reads done before overwriting xT
#pragma unroll
    for (int j = 0; j < 64; j++) {
        __nv_bfloat16 h, l; split_bf16(o[j], h, l);
        xhT[j * 128 + tid] = h; xlT[j * 128 + tid] = l;
    }
    stage_w<64>(wh, wl, w2, tid);
    __syncthreads();

    wmma_layer<4>(xhT, xlT, wh, wl, s_out, wid);

#pragma unroll
    for (int j = 0; j < 64; j++)
        o[j] = fmaxf(s_out[j * 128 + tid] + __ldg(b2 + j), 0.f);

    int node = nbase + tid;
    if (node < N_NODES) {
        int g = __ldg(gids + node);
        float4* hrow = reinterpret_cast<float4*>(g_h1 + (size_t)node * H_F);
        float*  srow = g_sum1 + (size_t)g * H_F;
#pragma unroll
        for (int jg = 0; jg < 16; jg++) {
            float4 v = make_float4(o[4 * jg], o[4 * jg + 1], o[4 * jg + 2], o[4 * jg + 3]);
            hrow[jg] = v;
            red_add_v4(srow + jg * 4, v);
        }
        atomicAdd(&g_cnt[g], 1.0f);
    }
}

// ============================================================================
// node MLP 2 (WMMA): x(64)=h1+agg2 -> relu(W1 64) -> relu(W2 64), pools sum2.
// ============================================================================
__global__ __launch_bounds__(128)
void mlp2_kernel(const float* __restrict__ w1, const float* __restrict__ b1,
                 const float* __restrict__ w2, const float* __restrict__ b2,
                 const int* __restrict__ gids) {
    __shared__ __align__(16) char arena[49152];
    __nv_bfloat16* xhT = reinterpret_cast<__nv_bfloat16*>(arena);
    __nv_bfloat16* xlT = reinterpret_cast<__nv_bfloat16*>(arena + 16384);
    __nv_bfloat16* wh  = reinterpret_cast<__nv_bfloat16*>(arena + 32768);
    __nv_bfloat16* wl  = reinterpret_cast<__nv_bfloat16*>(arena + 40960);
    float* s_out = reinterpret_cast<float*>(arena);
    const int tid = threadIdx.x, wid = tid >> 5;
    const int nbase = blockIdx.x * 128;

    // stage x = h1 + agg2, transposed bf16 hi/lo (K=64)
    for (int idx = tid; idx < 128 * 16; idx += 128) {
        int row = idx >> 4, c = idx & 15;
        int node = nbase + row;
        float4 v = make_float4(0.f, 0.f, 0.f, 0.f);
        if (node < N_NODES) {
            float4 a = *(reinterpret_cast<const float4*>(g_h1)   + (size_t)node * 16 + c);
            float4 b = *(reinterpret_cast<const float4*>(g_agg2) + (size_t)node * 16 + c);
            v = make_float4(a.x + b.x, a.y + b.y, a.z + b.z, a.w + b.w);
        }
        int col = c * 4;
        __nv_bfloat16 h, l;
        split_bf16(v.x, h, l); xhT[(col    ) * 128 + row] = h; xlT[(col    ) * 128 + row] = l;
        split_bf16(v.y, h, l); xhT[(col + 1) * 128 + row] = h; xlT[(col + 1) * 128 + row] = l;
        split_bf16(v.z, h, l); xhT[(col + 2) * 128 + row] = h; xlT[(col + 2) * 128 + row] = l;
        split_bf16(v.w, h, l); xhT[(col + 3) * 128 + row] = h; xlT[(col + 3) * 128 + row] = l;
    }
    stage_w<64>(wh, wl, w1, tid);
    __syncthreads();

    wmma_layer<4>(xhT, xlT, wh, wl, s_out, wid);

    float o[64];
#pragma unroll
    for (int j = 0; j < 64; j++)
        o[j] = fmaxf(s_out[j * 128 + tid] + __ldg(b1 + j), 0.f);
    __syncthreads();
#pragma unroll
    for (int j = 0; j < 64; j++) {
        __nv_bfloat16 h, l; split_bf16(o[j], h, l);
        xhT[j * 128 + tid] = h; xlT[j * 128 + tid] = l;
    }
    stage_w<64>(wh, wl, w2, tid);
    __syncthreads();

    wmma_layer<4>(xhT, xlT, wh, wl, s_out, wid);

#pragma unroll
    for (int j = 0; j < 64; j++)
        o[j] = fmaxf(s_out[j * 128 + tid] + __ldg(b2 + j), 0.f);

    int node = nbase + tid;
    if (node < N_NODES) {
        int g = __ldg(gids + node);
        float* srow = g_sum2 + (size_t)g * H_F;
#pragma unroll
        for (int jg = 0; jg < 16; jg++)
            red_add_v4(srow + jg * 4,
                       make_float4(o[4 * jg], o[4 * jg + 1], o[4 * jg + 2], o[4 * jg + 3]));
    }
}

// ---------------- final tower: 4 graphs per block + state re-zeroing ---------
#define GPB 4
__device__ __forceinline__ void lin4(const float (*x)[256], float (*y)[256],
                                     const float* __restrict__ w,
                                     const float* __restrict__ b,
                                     int nin, int nout, int t) {
    if (t < nout) {
        float a0 = b[t], a1 = a0, a2 = a0, a3 = a0;
        for (int i = 0; i < nin; i++) {
            float wv = __ldg(w + i * nout + t);
            a0 += wv * x[0][i];
            a1 += wv * x[1][i];
            a2 += wv * x[2][i];
            a3 += wv * x[3][i];
        }
        y[0][t] = fmaxf(a0, 0.f);
        y[1][t] = fmaxf(a1, 0.f);
        y[2][t] = fmaxf(a2, 0.f);
        y[3][t] = fmaxf(a3, 0.f);
    }
    __syncthreads();
}

__global__ __launch_bounds__(256)
void tower_kernel(const float* __restrict__ ev,
                  const float* __restrict__ l0w, const float* __restrict__ l0b,
                  const float* __restrict__ l1w, const float* __restrict__ l1b,
                  const float* __restrict__ l2w, const float* __restrict__ l2b,
                  const float* __restrict__ l3w, const float* __restrict__ l3b,
                  const float* __restrict__ l4w, const float* __restrict__ l4b,
                  const float* __restrict__ l5w, const float* __restrict__ l5b,
                  const float* __restrict__ l6w, const float* __restrict__ l6b,
                  float* __restrict__ out) {
    __shared__ float xa[GPB][256], xb[GPB][256];
    int g0 = blockIdx.x * GPB, t = threadIdx.x;

    if (t < 80) {
#pragma unroll
        for (int g = 0; g < GPB; g++) {
            int gg = g0 + g;
            if (t < H_F) {
                float c = fmaxf(g_cnt[gg], 1.f);
                xa[g][t] = (g_sum1[gg * H_F + t] + 2.f * g_sum2[gg * H_F + t]) / c;
            } else {
                xa[g][t] = __ldg(ev + gg * 16 + (t - 64));
            }
        }
    }
    __syncthreads();

    // re-zero state for next graph replay (reads above complete past barrier)
    g_sum1[g0 * H_F + t] = 0.f;
    g_sum2[g0 * H_F + t] = 0.f;
    if (t < GPB) g_cnt[g0 + t] = 0.f;
    for (int i = blockIdx.x * 256 + t; i < N_NODES; i += NB / GPB * 256)
        g_deg[i] = 0;
    if (blockIdx.x == 0 && t == 0) g_total = 0;

    lin4(xa, xb, l0w, l0b,  80, 256, t);
    lin4(xb, xa, l1w, l1b, 256, 128, t);
    lin4(xa, xb, l2w, l2b, 128, 128, t);
    lin4(xb, xa, l3w, l3b, 128,  64, t);
    lin4(xa, xb, l4w, l4b,  64,  64, t);
    lin4(xb, xa, l5w, l5b,  64,  32, t);

    if (t < GPB) {
        float s = l6b[0];
#pragma unroll
        for (int i = 0; i < 32; i++) s += xa[t][i] * __ldg(l6w + i);
        out[g0 + t] = s;
    }
}

// ---------------- launch -----------------------------------------------------
extern "C" void kernel_launch(void* const* d_in, const int* in_sizes, int n_in,
                              void* d_out, int out_size) {
    const float* in_feat = (const float*)d_in[0];
    const float* ev      = (const float*)d_in[1];
    const int*   src     = (const int*)  d_in[2];
    const int*   dst     = (const int*)  d_in[3];
    const int*   gids    = (const int*)  d_in[4];
    const float* c0w1 = (const float*)d_in[5];
    const float* c0b1 = (const float*)d_in[6];
    const float* c0w2 = (const float*)d_in[7];
    const float* c0b2 = (const float*)d_in[8];
    const float* c1w1 = (const float*)d_in[9];
    const float* c1b1 = (const float*)d_in[10];
    const float* c1w2 = (const float*)d_in[11];
    const float* c1b2 = (const float*)d_in[12];
    const float* l0w = (const float*)d_in[13]; const float* l0b = (const float*)d_in[14];
    const float* l1w = (const float*)d_in[15]; const float* l1b = (const float*)d_in[16];
    const float* l2w = (const float*)d_in[17]; const float* l2b = (const float*)d_in[18];
    const float* l3w = (const float*)d_in[19]; const float* l3b = (const float*)d_in[20];
    const float* l4w = (const float*)d_in[21]; const float* l4b = (const float*)d_in[22];
    const float* l5w = (const float*)d_in[23]; const float* l5b = (const float*)d_in[24];
    const float* l6w = (const float*)d_in[25]; const float* l6b = (const float*)d_in[26];
    float* out = (float*)d_out;

    deg_kernel <<<(N_EDGES + 255) / 256, 256>>>(dst);
    offs_kernel<<<(N_NODES + 255) / 256, 256>>>();
    fill_kernel<<<(N_EDGES + 255) / 256, 256>>>(src, dst);

    gather1_kernel<<<(N_NODES * 32 + 255) / 256, 256>>>(in_feat);
    mlp1_kernel<<<(N_NODES + 127) / 128, 128>>>(in_feat, c0w1, c0b1, c0w2, c0b2, gids);

    gather2_kernel<<<(N_NODES * 32 + 255) / 256, 256>>>();
    mlp2_kernel<<<(N_NODES + 127) / 128, 128>>>(c1w1, c1b1, c1w2, c1b2, gids);

    tower_kernel<<<NB / GPB, 256>>>(ev,
                                    l0w, l0b, l1w, l1b, l2w, l2b, l3w, l3b,
                                    l4w, l4b, l5w, l5b, l6w, l6b, out);
}